// round 5
// baseline (speedup 1.0000x reference)
#include <cuda_runtime.h>
#include <cuda_bf16.h>
#include <math.h>
#include <stdint.h>

// Problem constants
#define NSTEP 8
#define DSTEP 128
#define NEMBD 1024
#define VOCAB 50257
#define VPAD  50304            // 393 * 128
#define BB 2
#define TT 2039
#define KK 2048
#define MROWS (BB*KK)          // 4096
#define PRED_ROWS (BB*TT)      // 4078
#define EMB_ELEMS (BB*(KK-1)*NEMBD)

#define TILES_N 393
#define TILES_M 32
#define TOTAL_TILES (TILES_M * TILES_N)   // 12576
#define G2_GRID 148

// Scratch
__device__ __align__(256) float g_newx[MROWS * NEMBD];
__device__ double g_acc[2];
__device__ float g_rowsum[MROWS];
__device__ __align__(256) __nv_bfloat16 g_Xhi[(size_t)MROWS * NEMBD];
__device__ __align__(256) __nv_bfloat16 g_Xlo[(size_t)MROWS * NEMBD];
__device__ __align__(256) __nv_bfloat16 g_Whi[(size_t)NEMBD * NEMBD];  // [e][d]
__device__ __align__(256) __nv_bfloat16 g_Wlo[(size_t)NEMBD * NEMBD];
__device__ __align__(256) __nv_bfloat16 g_Bhi[(size_t)VPAD * DSTEP];
__device__ __align__(256) __nv_bfloat16 g_Blo[(size_t)VPAD * DSTEP];
__device__ __align__(256) __nv_bfloat16 g_Ahi[(size_t)MROWS * DSTEP];
__device__ __align__(256) __nv_bfloat16 g_Alo[(size_t)MROWS * DSTEP];

__device__ __forceinline__ uint32_t smem_u32(const void* p) {
    uint32_t a;
    asm("{ .reg .u64 t; cvta.to.shared.u64 t, %1; cvt.u32.u64 %0, t; }"
        : "=r"(a) : "l"(p));
    return a;
}

// ---------------------------------------------------------------------------
__global__ __launch_bounds__(256) void zero_kernel() {
    int i = blockIdx.x * 256 + threadIdx.x;
    if (i == 0) { g_acc[0] = 0.0; g_acc[1] = 0.0; }
    if (i < MROWS) g_rowsum[i] = 0.f;
}

// ---------------------------------------------------------------------------
// Build x in bf16 hi/lo, vectorized 4 elems/thread.
__global__ __launch_bounds__(256) void build_x_kernel(
    const float* __restrict__ noise, const float* __restrict__ left_noise,
    const float* __restrict__ right_noise, const float* __restrict__ wte,
    const float* __restrict__ wpe, const int* __restrict__ toks)
{
    int idx = (blockIdx.x * 256 + threadIdx.x) * 4;
    int e  = idx & (NEMBD - 1);
    int bk = idx >> 10;
    int k  = bk & (KK - 1);
    int b  = bk >> 11;
    int r  = e >> 7;
    int d  = e & (DSTEP - 1);
    int s  = k + r;

    float4 v;
    if (s < NSTEP) {
        v = *(const float4*)&left_noise[((b * NSTEP + s) * NSTEP + r) * DSTEP + d];
    } else if (s >= NSTEP + TT) {
        v = *(const float4*)&right_noise[((b * NSTEP + (s - NSTEP - TT)) * NSTEP + r) * DSTEP + d];
    } else {
        int t = s - NSTEP;
        float w = (float)(r + 1) * 0.125f;
        int tok = toks[b * TT + t];
        float4 emb = *(const float4*)&wte[(size_t)tok * DSTEP + d];
        float4 nz  = *(const float4*)&noise[(((size_t)b * TT + t) * NSTEP + r) * DSTEP + d];
        float iw = 1.0f - w;
        v = make_float4(emb.x * iw + nz.x * w, emb.y * iw + nz.y * w,
                        emb.z * iw + nz.z * w, emb.w * iw + nz.w * w);
    }
    float4 p = *(const float4*)&wpe[k * NEMBD + e];
    float f[4] = { v.x + p.x, v.y + p.y, v.z + p.z, v.w + p.w };
    __nv_bfloat16 hi[4], lo[4];
#pragma unroll
    for (int i = 0; i < 4; i++) {
        hi[i] = __float2bfloat16(f[i]);
        lo[i] = __float2bfloat16(f[i] - __bfloat162float(hi[i]));
    }
    *(uint2*)&g_Xhi[idx] = *(uint2*)hi;
    *(uint2*)&g_Xlo[idx] = *(uint2*)lo;
}

// ---------------------------------------------------------------------------
// Transpose W_bb -> [e][d] + split hi/lo.
__global__ __launch_bounds__(256) void conv_W_kernel(const float* __restrict__ W)
{
    __shared__ float t[32][33];
    int be = blockIdx.x * 32;
    int bd = blockIdx.y * 32;
    int tx = threadIdx.x & 31, ty = threadIdx.x >> 5;
#pragma unroll
    for (int i = 0; i < 32; i += 8)
        t[ty + i][tx] = W[(size_t)(bd + ty + i) * NEMBD + be + tx];
    __syncthreads();
#pragma unroll
    for (int i = 0; i < 32; i += 8) {
        float v = t[tx][ty + i];
        __nv_bfloat16 hi = __float2bfloat16(v);
        size_t o = (size_t)(be + ty + i) * NEMBD + bd + tx;
        g_Whi[o] = hi;
        g_Wlo[o] = __float2bfloat16(v - __bfloat162float(hi));
    }
}

// ---------------------------------------------------------------------------
// wte split hi/lo, vectorized.
__global__ __launch_bounds__(256) void conv_wte_kernel(const float* __restrict__ wte)
{
    size_t i4 = (size_t)blockIdx.x * 256 + threadIdx.x;
    size_t e = i4 * 4;
    size_t row = e >> 7;
    float4 v = make_float4(0.f, 0.f, 0.f, 0.f);
    if (row < VOCAB) v = *(const float4*)&wte[e];
    float f[4] = { v.x, v.y, v.z, v.w };
    __nv_bfloat16 hi[4], lo[4];
#pragma unroll
    for (int i = 0; i < 4; i++) {
        hi[i] = __float2bfloat16(f[i]);
        lo[i] = __float2bfloat16(f[i] - __bfloat162float(hi[i]));
    }
    *(uint2*)&g_Bhi[e] = *(uint2*)hi;
    *(uint2*)&g_Blo[e] = *(uint2*)lo;
}

// ---------------------------------------------------------------------------
// MMA helpers
#define ROWP 136
#define TILEB (128 * ROWP * 2)      // 34816 B
#define G1_SMEM (4 * TILEB)         // 139264
#define G2_SMEM (6 * TILEB)         // 208896

__device__ __forceinline__ void ldsm_x4(uint32_t* r, uint32_t addr) {
    asm volatile("ldmatrix.sync.aligned.m8n8.x4.shared.b16 {%0,%1,%2,%3}, [%4];"
                 : "=r"(r[0]), "=r"(r[1]), "=r"(r[2]), "=r"(r[3]) : "r"(addr));
}
__device__ __forceinline__ void mma16816(float* c, const uint32_t* a,
                                         uint32_t b0, uint32_t b1) {
    asm volatile("mma.sync.aligned.m16n8k16.row.col.f32.bf16.bf16.f32 "
                 "{%0,%1,%2,%3}, {%4,%5,%6,%7}, {%8,%9}, {%0,%1,%2,%3};"
                 : "+f"(c[0]), "+f"(c[1]), "+f"(c[2]), "+f"(c[3])
                 : "r"(a[0]), "r"(a[1]), "r"(a[2]), "r"(a[3]), "r"(b0), "r"(b1));
}
__device__ __forceinline__ void cp_commit() {
    asm volatile("cp.async.commit_group;" ::: "memory");
}
template <int N> __device__ __forceinline__ void cp_wait() {
    asm volatile("cp.async.wait_group %0;" :: "n"(N) : "memory");
}

// Sync load of a 128x128 bf16 tile (row stride src_stride bf16) into padded SMEM.
__device__ __forceinline__ void load_tile(uint32_t dst, const __nv_bfloat16* src,
                                          int src_stride, int tid) {
    const uint4* s = (const uint4*)src;
    int str4 = src_stride >> 3;
#pragma unroll
    for (int i = tid; i < 2048; i += 256) {
        int row = i >> 4, ch = i & 15;
        uint4 v = s[row * str4 + ch];
        uint32_t a = dst + row * (ROWP * 2) + ch * 16;
        asm volatile("st.shared.v4.b32 [%0], {%1,%2,%3,%4};"
                     :: "r"(a), "r"(v.x), "r"(v.y), "r"(v.z), "r"(v.w) : "memory");
    }
}

// Async load of a 128x128 bf16 tile with 256B contiguous rows (stride 128 bf16).
__device__ __forceinline__ void load_tile_cp(uint32_t dst, const __nv_bfloat16* src,
                                             int tid) {
    const char* s = (const char*)src;
#pragma unroll
    for (int i = tid; i < 2048; i += 256) {
        int row = i >> 4, ch = i & 15;
        uint32_t a = dst + row * (ROWP * 2) + ch * 16;
        asm volatile("cp.async.cg.shared.global [%0], [%1], 16;"
                     :: "r"(a), "l"(s + row * 256 + ch * 16) : "memory");
    }
}

// ---------------------------------------------------------------------------
// GEMM1 (HMMA): new_x = tanh(Xhi*Whi^T + Xlo*Whi^T + Xhi*Wlo^T)
__global__ __launch_bounds__(256, 1) void gemm1_mma_kernel()
{
    extern __shared__ char smem[];
    const uint32_t sb = smem_u32(smem);
    const uint32_t s_ah = sb, s_al = sb + TILEB;
    const uint32_t s_bh = sb + 2 * TILEB, s_bl = sb + 3 * TILEB;

    const int tid = threadIdx.x;
    const int w = tid >> 5, lane = tid & 31;
    const int bm = blockIdx.y * 128;
    const int bn = blockIdx.x * 128;

    const int warpM0 = (w & 3) * 32;
    const int warpN0 = (w >> 2) * 64;
    const int qr = lane & 7, sel = lane >> 3;

    uint32_t aoff[2], boff[4];
#pragma unroll
    for (int mi = 0; mi < 2; mi++) {
        int row = warpM0 + mi * 16 + qr + (sel & 1) * 8;
        aoff[mi] = row * (ROWP * 2) + ((sel >> 1) * 8) * 2;
    }
#pragma unroll
    for (int p = 0; p < 4; p++) {
        int row = warpN0 + p * 16 + qr + (sel >> 1) * 8;
        boff[p] = row * (ROWP * 2) + ((sel & 1) * 8) * 2;
    }

    float acc[2][8][4];
#pragma unroll
    for (int mi = 0; mi < 2; mi++)
#pragma unroll
        for (int ni = 0; ni < 8; ni++)
#pragma unroll
            for (int q = 0; q < 4; q++) acc[mi][ni][q] = 0.f;

    for (int kc = 0; kc < NEMBD; kc += 128) {
        load_tile(s_ah, g_Xhi + (size_t)bm * NEMBD + kc, NEMBD, tid);
        load_tile(s_al, g_Xlo + (size_t)bm * NEMBD + kc, NEMBD, tid);
        load_tile(s_bh, g_Whi + (size_t)bn * NEMBD + kc, NEMBD, tid);
        load_tile(s_bl, g_Wlo + (size_t)bn * NEMBD + kc, NEMBD, tid);
        __syncthreads();

        const uint32_t abase[3] = { s_ah, s_al, s_ah };
        const uint32_t bbase[3] = { s_bh, s_bh, s_bl };
#pragma unroll
        for (int prod = 0; prod < 3; prod++) {
            uint32_t ab = abase[prod], bb = bbase[prod];
#pragma unroll
            for (int ks = 0; ks < 8; ks++) {
                uint32_t koff = ks * 32;
                uint32_t af[2][4], bf[4][4];
#pragma unroll
                for (int mi = 0; mi < 2; mi++) ldsm_x4(af[mi], ab + aoff[mi] + koff);
#pragma unroll
                for (int p = 0; p < 4; p++) ldsm_x4(bf[p], bb + boff[p] + koff);
#pragma unroll
                for (int mi = 0; mi < 2; mi++)
#pragma unroll
                    for (int nt = 0; nt < 8; nt++)
                        mma16816(acc[mi][nt], af[mi],
                                 bf[nt >> 1][(nt & 1) * 2], bf[nt >> 1][(nt & 1) * 2 + 1]);
            }
        }
        __syncthreads();
    }

    const int r = lane >> 2, c2 = (lane & 3) * 2;
#pragma unroll
    for (int mi = 0; mi < 2; mi++) {
        int mb = bm + warpM0 + mi * 16;
#pragma unroll
        for (int h = 0; h < 2; h++) {
            int m = mb + r + h * 8;
#pragma unroll
            for (int ni = 0; ni < 8; ni++) {
                int n0 = bn + warpN0 + ni * 8 + c2;
                float t0 = tanhf(acc[mi][ni][h * 2 + 0]);
                float t1 = tanhf(acc[mi][ni][h * 2 + 1]);
                *(float2*)&g_newx[(size_t)m * NEMBD + n0] = make_float2(t0, t1);
                if (n0 < DSTEP) {
                    __nv_bfloat16 h0 = __float2bfloat16(t0);
                    __nv_bfloat16 h1 = __float2bfloat16(t1);
                    __nv_bfloat16 l0 = __float2bfloat16(t0 - __bfloat162float(h0));
                    __nv_bfloat16 l1 = __float2bfloat16(t1 - __bfloat162float(h1));
                    *(__nv_bfloat162*)&g_Ahi[(size_t)m * DSTEP + n0] =
                        __nv_bfloat162(h0, h1);
                    *(__nv_bfloat162*)&g_Alo[(size_t)m * DSTEP + n0] =
                        __nv_bfloat162(l0, l1);
                }
            }
        }
    }
}

// ---------------------------------------------------------------------------
// GEMM2 persistent (HMMA + cp.async double-buffered B, A cached per row-block).
// logits = Ahi*Bhi^T + Alo*Bhi^T + Ahi*Blo^T, fused exp-row-sum.
__global__ __launch_bounds__(256, 1) void gemm2_persist_kernel(float* __restrict__ OUT)
{
    extern __shared__ char smem[];
    const uint32_t sb = smem_u32(smem);
    const uint32_t s_ah = sb, s_al = sb + TILEB;
    const uint32_t s_bst[2] = { sb + 2 * TILEB, sb + 4 * TILEB };  // each: bh, bl

    const int tid = threadIdx.x;
    const int w = tid >> 5, lane = tid & 31;
    const int warpM0 = (w & 3) * 32;
    const int warpN0 = (w >> 2) * 64;
    const int qr = lane & 7, sel = lane >> 3;

    uint32_t aoff[2], boff[4];
#pragma unroll
    for (int mi = 0; mi < 2; mi++) {
        int row = warpM0 + mi * 16 + qr + (sel & 1) * 8;
        aoff[mi] = row * (ROWP * 2) + ((sel >> 1) * 8) * 2;
    }
#pragma unroll
    for (int p = 0; p < 4; p++) {
        int row = warpN0 + p * 16 + qr + (sel >> 1) * 8;
        boff[p] = row * (ROWP * 2) + ((sel & 1) * 8) * 2;
    }

    const int start = (int)(((long long)blockIdx.x * TOTAL_TILES) / G2_GRID);
    const int end   = (int)(((long long)(blockIdx.x + 1) * TOTAL_TILES) / G2_GRID);
    const int n = end - start;
    if (n <= 0) return;

    // Prologue: tile 0 (A + B into stage 0)
    {
        int t = start;
        int row = t / TILES_N, col = t - row * TILES_N;
        load_tile_cp(s_ah, g_Ahi + (size_t)row * 128 * DSTEP, tid);
        load_tile_cp(s_al, g_Alo + (size_t)row * 128 * DSTEP, tid);
        load_tile_cp(s_bst[0], g_Bhi + (size_t)col * 128 * DSTEP, tid);
        load_tile_cp(s_bst[0] + TILEB, g_Blo + (size_t)col * 128 * DSTEP, tid);
        cp_commit();
    }

    for (int idx = 0; idx < n; idx++) {
        int t = start + idx;
        int row = t / TILES_N, col = t - row * TILES_N;
        bool same = (idx + 1 < n) && (col + 1 < TILES_N);

        if (same) {
            // prefetch next B tile (same row) into the other stage
            uint32_t bb = s_bst[(idx + 1) & 1];
            load_tile_cp(bb, g_Bhi + (size_t)(col + 1) * 128 * DSTEP, tid);
            load_tile_cp(bb + TILEB, g_Blo + (size_t)(col + 1) * 128 * DSTEP, tid);
            cp_commit();
            cp_wait<1>();
        } else {
            cp_wait<0>();
        }
        __syncthreads();

        const uint32_t sbh = s_bst[idx & 1], sbl = sbh + TILEB;

        float acc[2][8][4];
#pragma unroll
        for (int mi = 0; mi < 2; mi++)
#pragma unroll
            for (int ni = 0; ni < 8; ni++)
#pragma unroll
                for (int q = 0; q < 4; q++) acc[mi][ni][q] = 0.f;

        const uint32_t abase[3] = { s_ah, s_al, s_ah };
        const uint32_t bbase[3] = { sbh, sbh, sbl };
#pragma unroll
        for (int prod = 0; prod < 3; prod++) {
            uint32_t ab = abase[prod], bb = bbase[prod];
#pragma unroll
            for (int ks = 0; ks < 8; ks++) {
                uint32_t koff = ks * 32;
                uint32_t af[2][4], bf[4][4];
#pragma unroll
                for (int mi = 0; mi < 2; mi++) ldsm_x4(af[mi], ab + aoff[mi] + koff);
#pragma unroll
                for (int p = 0; p < 4; p++) ldsm_x4(bf[p], bb + boff[p] + koff);
#pragma unroll
                for (int mi = 0; mi < 2; mi++)
#pragma unroll
                    for (int nt = 0; nt < 8; nt++)
                        mma16816(acc[mi][nt], af[mi],
                                 bf[nt >> 1][(nt & 1) * 2], bf[nt >> 1][(nt & 1) * 2 + 1]);
            }
        }
        __syncthreads();   // ldsm done before buffers are overwritten

        if (!same && idx + 1 < n) {
            // row change: load A(new row) + B into the other stage
            int t2 = t + 1;
            int row2 = t2 / TILES_N, col2 = t2 - row2 * TILES_N;
            load_tile_cp(s_ah, g_Ahi + (size_t)row2 * 128 * DSTEP, tid);
            load_tile_cp(s_al, g_Alo + (size_t)row2 * 128 * DSTEP, tid);
            uint32_t bb = s_bst[(idx + 1) & 1];
            load_tile_cp(bb, g_Bhi + (size_t)col2 * 128 * DSTEP, tid);
            load_tile_cp(bb + TILEB, g_Blo + (size_t)col2 * 128 * DSTEP, tid);
            cp_commit();
        }

        // Epilogue (overlaps in-flight prefetch)
        const int bm = row * 128, bv = col * 128;
        const int r = lane >> 2, c2 = (lane & 3) * 2;
        float rsum[2][2] = {{0.f, 0.f}, {0.f, 0.f}};
#pragma unroll
        for (int mi = 0; mi < 2; mi++) {
            int mb = bm + warpM0 + mi * 16;
            int m0 = mb + r, m1 = mb + r + 8;
            size_t ro0 = (size_t)m0 * VOCAB, ro1 = (size_t)m1 * VOCAB;
#pragma unroll
            for (int ni = 0; ni < 8; ni++) {
                int n0 = bv + warpN0 + ni * 8 + c2;
                bool v0 = n0 < VOCAB, v1 = (n0 + 1) < VOCAB;
                float c00 = acc[mi][ni][0], c01 = acc[mi][ni][1];
                float c10 = acc[mi][ni][2], c11 = acc[mi][ni][3];
                if (v0) { OUT[ro0 + n0] = c00; OUT[ro1 + n0] = c10; }
                if (v1) { OUT[ro0 + n0 + 1] = c01; OUT[ro1 + n0 + 1] = c11; }
                rsum[mi][0] += (v0 ? __expf(c00) : 0.f) + (v1 ? __expf(c01) : 0.f);
                rsum[mi][1] += (v0 ? __expf(c10) : 0.f) + (v1 ? __expf(c11) : 0.f);
            }
        }
#pragma unroll
        for (int mi = 0; mi < 2; mi++)
#pragma unroll
            for (int h = 0; h < 2; h++) {
                float s = rsum[mi][h];
                s += __shfl_xor_sync(0xFFFFFFFF, s, 1);
                s += __shfl_xor_sync(0xFFFFFFFF, s, 2);
                if ((lane & 3) == 0) {
                    int m = bm + warpM0 + mi * 16 + r + h * 8;
                    atomicAdd(&g_rowsum[m], s);
                }
            }
    }
}

// ---------------------------------------------------------------------------
__global__ __launch_bounds__(256) void nll_kernel(
    const float* __restrict__ logits, const int* __restrict__ toks)
{
    __shared__ float red[256];
    int row = blockIdx.x * 256 + threadIdx.x;
    float nll = 0.f;
    if (row < PRED_ROWS) {
        int b = row / TT;
        int j = row - b * TT;
        int m = b * KK + j + NSTEP;
        int tgt = toks[row];
        nll = logf(g_rowsum[m]) - logits[(size_t)m * VOCAB + tgt];
    }
    red[threadIdx.x] = nll;
    __syncthreads();
    for (int off = 128; off > 0; off >>= 1) {
        if (threadIdx.x < off) red[threadIdx.x] += red[threadIdx.x + off];
        __syncthreads();
    }
    if (threadIdx.x == 0) atomicAdd(&g_acc[0], (double)red[0]);
}

// ---------------------------------------------------------------------------
__global__ __launch_bounds__(256) void emb_loss_kernel() {
    __shared__ float red[256];
    float s = 0.f;
    const int total4 = EMB_ELEMS / 4;
    for (int i4 = blockIdx.x * 256 + threadIdx.x; i4 < total4;
         i4 += gridDim.x * 256) {
        int elem = i4 * 4;
        int b = elem / ((KK - 1) * NEMBD);
        int rem = elem - b * ((KK - 1) * NEMBD);
        int k = rem >> 10;
        int e = rem & (NEMBD - 1);
        size_t base = ((size_t)(b * KK + k)) * NEMBD + e;
        float4 a = *(const float4*)&g_newx[base];
        float4 c = *(const float4*)&g_newx[base + NEMBD];
        float dx = a.x - c.x, dy = a.y - c.y, dz = a.z - c.z, dw = a.w - c.w;
        s += dx * dx + dy * dy + dz * dz + dw * dw;
    }
    red[threadIdx.x] = s;
    __syncthreads();
    for (int off = 128; off > 0; off >>= 1) {
        if (threadIdx.x < off) red[threadIdx.x] += red[threadIdx.x + off];
        __syncthreads();
    }
    if (threadIdx.x == 0) atomicAdd(&g_acc[1], (double)red[0]);
}

// ---------------------------------------------------------------------------
__global__ void finalize_kernel(float* out, long long loss_idx) {
    double loss = g_acc[0] / (double)PRED_ROWS + g_acc[1] / (double)EMB_ELEMS;
    out[loss_idx] = (float)loss;
}

// ---------------------------------------------------------------------------
extern "C" void kernel_launch(void* const* d_in, const int* in_sizes, int n_in,
                              void* d_out, int out_size) {
    const float* noise       = (const float*)d_in[0];
    const float* left_noise  = (const float*)d_in[1];
    const float* right_noise = (const float*)d_in[2];
    const float* wte         = (const float*)d_in[3];
    const float* wpe         = (const float*)d_in[4];
    const float* W_bb        = (const float*)d_in[5];
    const int*   toks        = (const int*)d_in[6];
    float* out = (float*)d_out;

    static int smem_set = 0;
    if (!smem_set) {
        cudaFuncSetAttribute(gemm1_mma_kernel,
                             cudaFuncAttributeMaxDynamicSharedMemorySize, G1_SMEM);
        cudaFuncSetAttribute(gemm2_persist_kernel,
                             cudaFuncAttributeMaxDynamicSharedMemorySize, G2_SMEM);
        smem_set = 1;
    }

    zero_kernel<<<MROWS / 256, 256>>>();

    build_x_kernel<<<(MROWS * NEMBD) / 1024, 256>>>(noise, left_noise, right_noise,
                                                    wte, wpe, toks);
    conv_W_kernel<<<dim3(32, 32), 256>>>(W_bb);
    conv_wte_kernel<<<(VPAD * DSTEP) / 1024, 256>>>(wte);

    gemm1_mma_kernel<<<dim3(NEMBD / 128, MROWS / 128), 256, G1_SMEM>>>();

    gemm2_persist_kernel<<<G2_GRID, 256, G2_SMEM>>>(out);

    nll_kernel<<<(PRED_ROWS + 255) / 256, 256>>>(out, toks);

    emb_loss_kernel<<<1024, 256>>>();

    long long nlog = (long long)MROWS * VOCAB;
    if ((long long)out_size > nlog) {
        finalize_kernel<<<1, 1>>>(out, (long long)out_size - 1);
    }
}